// round 14
// baseline (speedup 1.0000x reference)
#include <cuda_runtime.h>
#include <cuda_bf16.h>
#include <mma.h>
#include <math.h>

using namespace nvcuda;

#define BB 2
#define TT 512
#define MMs 512
#define DDim 512
#define HH 8
#define UU 64
#define KVL 1024
#define LARGE_BIAS 10000.0f

// ---------------- scratch ----------------
__device__ __align__(128) float g_vrel[HH * DDim];
__device__ __align__(128) float g_ubias[BB * HH * KVL];
__device__ __align__(128) float g_logits[16 * TT * KVL];
__device__ __align__(128) float2 g_qtrig[TT * DDim];
// bf16 hi/lo pools
__device__ __align__(128) __nv_bfloat16 g_inh[BB * TT * DDim], g_inl[BB * TT * DDim];
__device__ __align__(128) __nv_bfloat16 g_conh[BB * KVL * DDim], g_conl[BB * KVL * DDim];
__device__ __align__(128) __nv_bfloat16 g_qWh[512 * 512], g_qWl[512 * 512];
__device__ __align__(128) __nv_bfloat16 g_kvWh[512 * 1024], g_kvWl[512 * 1024];
__device__ __align__(128) __nv_bfloat16 g_oWh[512 * 512], g_oWl[512 * 512];
__device__ __align__(128) __nv_bfloat16 g_relh[512 * 512], g_rell[512 * 512];
__device__ __align__(128) __nv_bfloat16 g_qh[BB * TT * 512], g_ql[BB * TT * 512];
__device__ __align__(128) __nv_bfloat16 g_valh[BB * KVL * 512], g_vall[BB * KVL * 512];
__device__ __align__(128) __nv_bfloat16 g_atth[BB * TT * 512], g_attl[BB * TT * 512];
__device__ __align__(128) __nv_bfloat16 g_Wh[16 * TT * KVL], g_Wl[16 * TT * KVL];
__device__ __align__(128) __nv_bfloat16 g_Ktrig_h[KVL * 1024], g_Ktrig_l[KVL * 1024];
__device__ __align__(128) __nv_bfloat16 g_Bkey_h[16 * KVL * UU], g_Bkey_l[16 * KVL * UU];
__device__ __align__(128) __nv_bfloat16 g_Acat_h[16 * TT * 1088], g_Acat_l[16 * TT * 1088];

__device__ __forceinline__ void bsplit(float x, __nv_bfloat16& h, __nv_bfloat16& l) {
    h = __float2bfloat16(x);
    l = __float2bfloat16(x - __bfloat162float(h));
}
__device__ __forceinline__ void cpa16(void* sdst, const void* gsrc) {
    unsigned s = (unsigned)__cvta_generic_to_shared(sdst);
    asm volatile("cp.async.cg.shared.global [%0], [%1], 16;" :: "r"(s), "l"(gsrc));
}
#define CP_COMMIT() asm volatile("cp.async.commit_group;" ::: "memory")
#define CP_WAIT1()  asm volatile("cp.async.wait_group 1;" ::: "memory")
#define CP_WAIT0()  asm volatile("cp.async.wait_group 0;" ::: "memory")
__device__ __forceinline__ float ex2f(float x) {
    float r;
    asm("ex2.approx.ftz.f32 %0, %1;" : "=f"(r) : "f"(x));
    return r;
}

// ---------------- prep1 (14848 blocks) ----------------
__global__ void __launch_bounds__(256) k_prep1(
    const float* __restrict__ in, const float* __restrict__ st,
    const float* __restrict__ rW, const float* __restrict__ vv,
    const float* __restrict__ qW, const float* __restrict__ kW,
    const float* __restrict__ vW, const float* __restrict__ oW)
{
    int blk = blockIdx.x;
    int tid = threadIdx.x;
    if (blk < 4096) {
        int i = blk * 256 + tid;
        int d = i & 511, j = (i >> 9) & 1023, b = i >> 19;
        float v = (j < MMs) ? st[((size_t)(b * MMs + j)) * 512 + d]
                            : in[((size_t)(b * TT + (j - MMs))) * 512 + d];
        __nv_bfloat16 hi, lo; bsplit(v, hi, lo);
        g_conh[i] = hi; g_conl[i] = lo;
        return;
    }
    blk -= 4096;
    if (blk < 1024) {
        int i = blk * 256 + tid;
        __nv_bfloat16 hi, lo; bsplit(rW[i], hi, lo);
        size_t o = (size_t)(i & 511) * 512 + (i >> 9);
        g_relh[o] = hi; g_rell[o] = lo;
        return;
    }
    blk -= 1024;
    if (blk < 512) {
        int g = (blk * 256 + tid) >> 5, lane = tid & 31;
        int h = g >> 9, d = g & 511;
        const float* rp = rW + (size_t)d * 512 + h * 64;
        const float* vp = vv + h * 64;
        float s = rp[lane] * vp[lane] + rp[lane + 32] * vp[lane + 32];
#pragma unroll
        for (int o = 16; o > 0; o >>= 1) s += __shfl_xor_sync(~0u, s, o);
        if (!lane) g_vrel[h * 512 + d] = s;
        return;
    }
    blk -= 512;
    if (blk < 1024) {
        int i = blk * 256 + tid;
        int d = i & 511, qt = i >> 9;
        float invw = powf(10000.0f, -2.0f * (float)d / 512.0f);
        float off = (d & 1) ? 1.57079632679489662f : 0.0f;
        float s, c;
        sincosf((float)(qt + 512) * invw + off, &s, &c);
        g_qtrig[i] = make_float2(s, c);
        return;
    }
    blk -= 1024;
    if (blk < 2048) {
        int i = blk * 256 + tid;
        int d = i & 511, kv = i >> 9;
        float invw = powf(10000.0f, -2.0f * (float)d / 512.0f);
        float s, c;
        sincosf((float)kv * invw, &s, &c);
        __nv_bfloat16 ch, cl, sh, sl;
        bsplit(c, ch, cl); bsplit(s, sh, sl);
        __nv_bfloat162 vh, vl;
        vh.x = ch; vh.y = sh; vl.x = cl; vl.y = sl;
        *(__nv_bfloat162*)&g_Ktrig_h[(size_t)kv * 1024 + 2 * d] = vh;
        *(__nv_bfloat162*)&g_Ktrig_l[(size_t)kv * 1024 + 2 * d] = vl;
        return;
    }
    blk -= 2048;
    if (blk < 2048) {
        int i = blk * 256 + tid;
        __nv_bfloat16 hi, lo; bsplit(in[i], hi, lo);
        g_inh[i] = hi; g_inl[i] = lo;
        return;
    }
    blk -= 2048;
    if (blk < 1024) {
        int i = blk * 256 + tid;
        __nv_bfloat16 hi, lo; bsplit(qW[i], hi, lo);
        g_qWh[i] = hi; g_qWl[i] = lo;
        return;
    }
    blk -= 1024;
    if (blk < 2048) {
        int i = blk * 256 + tid;
        int d = i >> 10, c = i & 1023;
        float x = (c < 512) ? kW[d * 512 + c] : vW[d * 512 + (c - 512)];
        __nv_bfloat16 hi, lo; bsplit(x, hi, lo);
        g_kvWh[i] = hi; g_kvWl[i] = lo;
        return;
    }
    blk -= 2048;
    {
        int i = blk * 256 + tid;
        __nv_bfloat16 hi, lo; bsplit(oW[i], hi, lo);
        g_oWh[i] = hi; g_oWl[i] = lo;
    }
}

// ---------------- ubias from bkey (64 blocks) ----------------
__global__ void __launch_bounds__(256) k_ubias(const float* __restrict__ uW) {
    int i = blockIdx.x * 256 + threadIdx.x;         // 16384 = 16*1024
    int kv = i & 1023, bh = i >> 10;
    int h = bh & 7;
    const __nv_bfloat16* kh = g_Bkey_h + ((size_t)bh * 1024 + kv) * 64;
    const __nv_bfloat16* kl = g_Bkey_l + ((size_t)bh * 1024 + kv) * 64;
    const float* up = uW + h * 64;
    float s = 0.f;
#pragma unroll
    for (int u = 0; u < 64; u++)
        s = fmaf(__bfloat162float(kh[u]) + __bfloat162float(kl[u]), up[u], s);
    g_ubias[i] = s;
}

// ---------------- WMMA hi/lo GEMM, cp.async 2-stage pipelined, fused epilogues ----------------
// emode: 0=fp32 C | 1=bf16 Chh/Cll | 2=query(qh/ql+Acat_c) | 3=keyval(bkey+val) | 4=qv(trig->Acat_p)
#define PADA 40
#define PADB 72
#define OUTLD 20
#define GA 10240
#define GB 4608
#define GSTG (2 * GA + 2 * GB)

__global__ void __launch_bounds__(256) gemmw(
    const __nv_bfloat16* __restrict__ Ah, const __nv_bfloat16* __restrict__ Al,
    const __nv_bfloat16* __restrict__ Bh, const __nv_bfloat16* __restrict__ Bl,
    float* __restrict__ C,
    __nv_bfloat16* __restrict__ Chh, __nv_bfloat16* __restrict__ Cll,
    int lda, int ldb, int ldc, int Kdim,
    long az1, long az2, long bz1, long bz2, long cz1, long cz2, int Z2,
    const int* __restrict__ rowmask, const float* __restrict__ bias, long biasz2,
    int causal, int emode)
{
    extern __shared__ char dsm[];
    int z = blockIdx.z, z1 = z / Z2, z2 = z - z1 * Z2;
    const __nv_bfloat16* Ahp = Ah + (size_t)z1 * az1 + (size_t)z2 * az2;
    const __nv_bfloat16* Alp = Al + (size_t)z1 * az1 + (size_t)z2 * az2;
    const __nv_bfloat16* Bhp = Bh + (size_t)z1 * bz1 + (size_t)z2 * bz2;
    const __nv_bfloat16* Blp = Bl + (size_t)z1 * bz1 + (size_t)z2 * bz2;
    size_t coff = (size_t)z1 * cz1 + (size_t)z2 * cz2;
    const float* biasp = bias ? (bias + (size_t)z2 * biasz2) : (const float*)0;

    int m0 = blockIdx.y * 128, n0 = blockIdx.x * 64;
    int tid = threadIdx.x, wid = tid >> 5, lane = tid & 31;
    int wy = wid >> 1, wx = wid & 1;

    wmma::fragment<wmma::accumulator, 16, 16, 16, float> acc[2][2];
#pragma unroll
    for (int mi = 0; mi < 2; mi++)
#pragma unroll
        for (int ni = 0; ni < 2; ni++) wmma::fill_fragment(acc[mi][ni], 0.f);

    int Klim = Kdim;
    if (causal) {
        int km = m0 + 640;
        Klim = (km < Kdim) ? ((km + 31) & ~31) : Kdim;
    }
    int nCh = Klim >> 5;

    auto issue = [&](int c, int s) {
        int kc = c * 32;
        char* base = dsm + s * GSTG;
#pragma unroll
        for (int t = tid; t < 512; t += 256) {
            int row = t >> 2, seg = (t & 3) * 8;
            size_t go = (size_t)(m0 + row) * lda + kc + seg;
            size_t so = ((size_t)row * PADA + seg) * 2;
            cpa16(base + so, Ahp + go);
            cpa16(base + GA + so, Alp + go);
        }
        {
            int row = tid >> 3, seg = (tid & 7) * 8;
            size_t go = (size_t)(kc + row) * ldb + n0 + seg;
            size_t so = ((size_t)row * PADB + seg) * 2;
            cpa16(base + 2 * GA + so, Bhp + go);
            cpa16(base + 2 * GA + GB + so, Blp + go);
        }
        CP_COMMIT();
    };

    issue(0, 0);
    for (int c = 0; c < nCh; c++) {
        if (c + 1 < nCh) { issue(c + 1, (c + 1) & 1); CP_WAIT1(); }
        else             { CP_WAIT0(); }
        __syncthreads();
        char* base = dsm + (c & 1) * GSTG;
        __nv_bfloat16* sAh = (__nv_bfloat16*)base;
        __nv_bfloat16* sAl = (__nv_bfloat16*)(base + GA);
        __nv_bfloat16* sBh = (__nv_bfloat16*)(base + 2 * GA);
        __nv_bfloat16* sBl = (__nv_bfloat16*)(base + 2 * GA + GB);
#pragma unroll
        for (int ks = 0; ks < 2; ks++) {
            wmma::fragment<wmma::matrix_a, 16, 16, 16, __nv_bfloat16, wmma::row_major> fah[2], fal[2];
            wmma::fragment<wmma::matrix_b, 16, 16, 16, __nv_bfloat16, wmma::row_major> fbh[2], fbl[2];
#pragma unroll
            for (int mi = 0; mi < 2; mi++) {
                wmma::load_matrix_sync(fah[mi], &sAh[(wy * 32 + mi * 16) * PADA + ks * 16], PADA);
                wmma::load_matrix_sync(fal[mi], &sAl[(wy * 32 + mi * 16) * PADA + ks * 16], PADA);
            }
#pragma unroll
            for (int ni = 0; ni < 2; ni++) {
                wmma::load_matrix_sync(fbh[ni], &sBh[ks * 16 * PADB + wx * 32 + ni * 16], PADB);
                wmma::load_matrix_sync(fbl[ni], &sBl[ks * 16 * PADB + wx * 32 + ni * 16], PADB);
            }
#pragma unroll
            for (int mi = 0; mi < 2; mi++)
#pragma unroll
                for (int ni = 0; ni < 2; ni++) {
                    wmma::mma_sync(acc[mi][ni], fah[mi], fbh[ni], acc[mi][ni]);
                    wmma::mma_sync(acc[mi][ni], fah[mi], fbl[ni], acc[mi][ni]);
                    wmma::mma_sync(acc[mi][ni], fal[mi], fbh[ni], acc[mi][ni]);
                }
        }
        __syncthreads();
    }

    float* sOut = (float*)dsm + wid * 16 * OUTLD;
#pragma unroll
    for (int mi = 0; mi < 2; mi++)
#pragma unroll
        for (int ni = 0; ni < 2; ni++) {
            wmma::store_matrix_sync(sOut, acc[mi][ni], OUTLD, wmma::mem_row_major);
            __syncwarp();
#pragma unroll
            for (int e = 0; e < 8; e++) {
                int idx = lane * 8 + e;
                int r = idx >> 4, cc = idx & 15;
                int mg = m0 + wy * 32 + mi * 16 + r;
                int ng = n0 + wx * 32 + ni * 16 + cc;
                float x = sOut[r * OUTLD + cc];
                if (biasp) x += biasp[ng];
                if (rowmask) x *= rowmask[mg] ? 1.f : 0.f;
                size_t oi = coff + (size_t)mg * ldc + ng;
                if (emode == 0) {
                    C[oi] = x;
                } else if (emode == 1) {
                    __nv_bfloat16 hi, lo; bsplit(x, hi, lo);
                    Chh[oi] = hi; Cll[oi] = lo;
                } else if (emode == 2) {          // query -> qh/ql + Acat_c
                    __nv_bfloat16 hi, lo; bsplit(x, hi, lo);
                    g_qh[oi] = hi; g_ql[oi] = lo;
                    int b = mg >> 9, qt = mg & 511, h = ng >> 6, u = ng & 63;
                    size_t o2 = ((size_t)(b * 8 + h) * 512 + qt) * 1088 + u;
                    g_Acat_h[o2] = hi; g_Acat_l[o2] = lo;
                } else if (emode == 3) {          // keyval -> bkey / val
                    int b = mg >> 10, kv = mg & 1023;
                    __nv_bfloat16 hi, lo; bsplit(x, hi, lo);
                    if (ng < 512) {
                        int h = ng >> 6, u = ng & 63;
                        size_t o2 = ((size_t)(b * 8 + h) * 1024 + kv) * 64 + u;
                        g_Bkey_h[o2] = hi; g_Bkey_l[o2] = lo;
                    } else {
                        size_t o2 = (size_t)mg * 512 + (ng - 512);
                        g_valh[o2] = hi; g_vall[o2] = lo;
                    }
                } else {                          // 4: qv -> Acat_p (trig rotate)
                    int b = mg >> 9, qt = mg & 511;
                    float2 tr = g_qtrig[qt * 512 + ng];
                    __nv_bfloat16 sh, sl, ch2, cl2;
                    bsplit(x * tr.x, sh, sl);
                    bsplit(-x * tr.y, ch2, cl2);
                    size_t o2 = ((size_t)(b * 8 + z2) * 512 + qt) * 1088 + 64 + 2 * ng;
                    __nv_bfloat162 vh, vl;
                    vh.x = sh; vh.y = ch2; vl.x = sl; vl.y = cl2;
                    *(__nv_bfloat162*)&g_Acat_h[o2] = vh;
                    *(__nv_bfloat162*)&g_Acat_l[o2] = vl;
                }
            }
            __syncwarp();
        }
}

// ---------------- WMMA logits (proven 128x128, 2-stage cp.async) ----------------
#define LTILE 10240
#define LSTG  (4 * LTILE)

__global__ void __launch_bounds__(256, 1) k_logits_wmma(
    const int* __restrict__ qmask, const int* __restrict__ smask)
{
    extern __shared__ char dsm[];
    int tid = threadIdx.x, wid = tid >> 5, lane = tid & 31;
    int kv0 = blockIdx.x * 128, qt0 = blockIdx.y * 128, bh = blockIdx.z;
    int b = bh >> 3;

    if (kv0 >= qt0 + 640) {
        float4 neg = make_float4(-LARGE_BIAS, -LARGE_BIAS, -LARGE_BIAS, -LARGE_BIAS);
        for (int t = tid; t < 128 * 32; t += 256) {
            int r = t >> 5, c = (t & 31) * 4;
            *(float4*)&g_logits[((size_t)bh * TT + qt0 + r) * KVL + kv0 + c] = neg;
        }
        return;
    }

    int wy = wid >> 2, wx = wid & 3;
    wmma::fragment<wmma::accumulator, 16, 16, 16, float> acc[4][2];
#pragma unroll
    for (int mi = 0; mi < 4; mi++)
#pragma unroll
        for (int ni = 0; ni < 2; ni++) wmma::fill_fragment(acc[mi][ni], 0.f);

    const __nv_bfloat16* Ah = g_Acat_h + ((size_t)bh * TT + qt0) * 1088;
    const __nv_bfloat16* Al = g_Acat_l + ((size_t)bh * TT + qt0) * 1088;
    const __nv_bfloat16* BKh = g_Bkey_h + (size_t)bh * KVL * 64;
    const __nv_bfloat16* BKl = g_Bkey_l + (size_t)bh * KVL * 64;

    auto issue = [&](int kc, int s) {
        const __nv_bfloat16 *Bhp, *Blp;
        size_t bld;
        int bcol;
        if (kc < 2) { Bhp = BKh; Blp = BKl; bld = 64; bcol = kc * 32; }
        else        { Bhp = g_Ktrig_h; Blp = g_Ktrig_l; bld = 1024; bcol = (kc - 2) * 32; }
        char* base = dsm + s * LSTG;
#pragma unroll
        for (int t = tid; t < 512; t += 256) {
            int row = t >> 2, seg = (t & 3) * 8;
            size_t so = ((size_t)row * PADA + seg) * 2;
            cpa16(base + so,             Ah + (size_t)row * 1088 + kc * 32 + seg);
            cpa16(base + LTILE + so,     Al + (size_t)row * 1088 + kc * 32 + seg);
            cpa16(base + 2 * LTILE + so, Bhp + (size_t)(kv0 + row) * bld + bcol + seg);
            cpa16(base + 3 * LTILE + so, Blp + (size_t)(kv0 + row) * bld + bcol + seg);
        }
        CP_COMMIT();
    };

    issue(0, 0);
    for (int kc = 0; kc < 34; kc++) {
        if (kc + 1 < 34) { issue(kc + 1, (kc + 1) & 1); CP_WAIT1(); }
        else             { CP_WAIT0(); }
        __syncthreads();
        char* base = dsm + (kc & 1) * LSTG;
        __nv_bfloat16* sAh = (__nv_bfloat16*)base;
        __nv_bfloat16* sAl = (__nv_bfloat16*)(base + LTILE);
        __nv_bfloat16* sBh = (__nv_bfloat16*)(base + 2 * LTILE);
        __nv_bfloat16* sBl = (__nv_bfloat16*)(base + 3 * LTILE);
#pragma unroll
        for (int ks = 0; ks < 2; ks++) {
            wmma::fragment<wmma::matrix_b, 16, 16, 16, __nv_bfloat16, wmma::col_major> fbh[2], fbl[2];
#pragma unroll
            for (int ni = 0; ni < 2; ni++) {
                wmma::load_matrix_sync(fbh[ni], &sBh[(wx * 32 + ni * 16) * PADA + ks * 16], PADA);
                wmma::load_matrix_sync(fbl[ni], &sBl[(wx * 32 + ni * 16) * PADA + ks * 16], PADA);
            }
#pragma unroll
            for (int mi = 0; mi < 4; mi++) {
                wmma::fragment<wmma::matrix_a, 16, 16, 16, __nv_bfloat16, wmma::row_major> fah, fal;
                wmma::load_matrix_sync(fah, &sAh[(wy * 64 + mi * 16) * PADA + ks * 16], PADA);
                wmma::load_matrix_sync(fal, &sAl[(wy * 64 + mi * 16) * PADA + ks * 16], PADA);
#pragma unroll
                for (int ni = 0; ni < 2; ni++) {
                    wmma::mma_sync(acc[mi][ni], fah, fbh[ni], acc[mi][ni]);
                    wmma::mma_sync(acc[mi][ni], fah, fbl[ni], acc[mi][ni]);
                    wmma::mma_sync(acc[mi][ni], fal, fbh[ni], acc[mi][ni]);
                }
            }
        }
        __syncthreads();
    }

    float* sOut = (float*)dsm + wid * 16 * OUTLD;
    const float* ub = g_ubias + (size_t)bh * KVL;
#pragma unroll
    for (int mi = 0; mi < 4; mi++)
#pragma unroll
        for (int ni = 0; ni < 2; ni++) {
            wmma::store_matrix_sync(sOut, acc[mi][ni], OUTLD, wmma::mem_row_major);
            __syncwarp();
#pragma unroll
            for (int e = 0; e < 8; e++) {
                int idx = lane * 8 + e;
                int r = idx >> 4, c = idx & 15;
                int qt = qt0 + wy * 64 + mi * 16 + r;
                int kv = kv0 + wx * 32 + ni * 16 + c;
                float x = (sOut[r * OUTLD + c] + ub[kv]) * 0.125f;
                if (kv - qt >= 513) x -= LARGE_BIAS;
                int cm = (kv < MMs) ? smask[b * MMs + kv] : qmask[b * TT + (kv - MMs)];
                if (!cm) x -= LARGE_BIAS;
                g_logits[((size_t)bh * TT + qt) * KVL + kv] = x;
            }
            __syncwarp();
        }
}

// ---------------- softmax: warp-per-row -> bf16 hi/lo weights ----------------
__global__ void __launch_bounds__(256) k_softmax() {
    int wid = threadIdx.x >> 5, lane = threadIdx.x & 31;
    size_t ro = ((size_t)blockIdx.x * 8 + wid) * KVL;
    const float* row = g_logits + ro;

    float4 v[8];
#pragma unroll
    for (int i = 0; i < 8; i++) v[i] = *(const float4*)&row[i * 128 + lane * 4];

    float mx = -1e30f;
#pragma unroll
    for (int i = 0; i < 8; i++)
        mx = fmaxf(mx, fmaxf(fmaxf(v[i].x, v[i].y), fmaxf(v[i].z, v[i].w)));
#pragma unroll
    for (int o = 16; o > 0; o >>= 1) mx = fmaxf(mx, __shfl_xor_sync(~0u, mx, o));

    float s = 0.f;
#pragma unroll
    for (int i = 0; i < 8; i++) {
        v[i].x = ex2f((v[i].x - mx) * 1.44269504f);
        v[i].y = ex2f((v[i].y - mx) * 1.44269504f);
        v[i].z = ex2f((v[i].z - mx) * 1.44269504f);
        v[i].w = ex2f((v[i].w - mx) * 1.44269504f);
        s += v[i].x + v[i].y + v[i].z + v[i].w;
    }
#pragma unroll
    for (int o = 16; o > 0; o >>= 1) s += __shfl_xor_sync(~0u, s, o);
    float inv = 1.f / s;

#pragma unroll
    for (int i = 0; i < 8; i++) {
        float w0 = v[i].x * inv, w1 = v[i].y * inv, w2 = v[i].z * inv, w3 = v[i].w * inv;
        __nv_bfloat16 h0, l0, h1, l1, h2, l2, h3, l3;
        bsplit(w0, h0, l0); bsplit(w1, h1, l1);
        bsplit(w2, h2, l2); bsplit(w3, h3, l3);
        __nv_bfloat162 ph0, ph1, pl0, pl1;
        ph0.x = h0; ph0.y = h1; ph1.x = h2; ph1.y = h3;
        pl0.x = l0; pl0.y = l1; pl1.x = l2; pl1.y = l3;
        size_t o = ro + i * 128 + lane * 4;
        *(__nv_bfloat162*)&g_Wh[o] = ph0;
        *(__nv_bfloat162*)&g_Wh[o + 2] = ph1;
        *(__nv_bfloat162*)&g_Wl[o] = pl0;
        *(__nv_bfloat162*)&g_Wl[o + 2] = pl1;
    }
}

// ---------------- host ----------------
static float* symaddr(const void* s) { void* p = 0; cudaGetSymbolAddress(&p, s); return (float*)p; }
static __nv_bfloat16* symaddrb(const void* s) { void* p = 0; cudaGetSymbolAddress(&p, s); return (__nv_bfloat16*)p; }

extern "C" void kernel_launch(void* const* d_in, const int* in_sizes, int n_in,
                              void* d_out, int out_size) {
    (void)in_sizes; (void)n_in; (void)out_size;
    const float* inputs = (const float*)d_in[0];
    const float* state  = (const float*)d_in[1];
    const int* mask     = (const int*)d_in[2];
    const int* smask    = (const int*)d_in[3];
    const float* qW = (const float*)d_in[4];
    const float* kW = (const float*)d_in[5];
    const float* rW = (const float*)d_in[6];
    const float* vW = (const float*)d_in[7];
    const float* uW = (const float*)d_in[8];
    const float* vv = (const float*)d_in[9];
    const float* oW = (const float*)d_in[10];
    float* out = (float*)d_out;

    float* pVrel = symaddr(g_vrel);

    __nv_bfloat16 *inh = symaddrb(g_inh), *inl = symaddrb(g_inl);
    __nv_bfloat16 *conh = symaddrb(g_conh), *conl = symaddrb(g_conl);
    __nv_bfloat16 *qWh = symaddrb(g_qWh), *qWl = symaddrb(g_qWl);
    __nv_bfloat16 *kvWh = symaddrb(g_kvWh), *kvWl = symaddrb(g_kvWl);
    __nv_bfloat16 *oWh = symaddrb(g_oWh), *oWl = symaddrb(g_oWl);
    __nv_bfloat16 *relh = symaddrb(g_relh), *rell = symaddrb(g_rell);
    __nv_bfloat16 *qh = symaddrb(g_qh), *ql = symaddrb(g_ql);
    __nv_bfloat16 *valh = symaddrb(g_valh), *vall = symaddrb(g_vall);
    __nv_bfloat16 *atth = symaddrb(g_atth), *attl = symaddrb(g_attl);
    __nv_bfloat16 *Wh = symaddrb(g_Wh), *Wl = symaddrb(g_Wl);

    const int* nomask = (const int*)0;
    const float* nobias = (const float*)0;
    __nv_bfloat16* nobf = (__nv_bfloat16*)0;
    float* nof = (float*)0;

    cudaFuncSetAttribute(k_logits_wmma, cudaFuncAttributeMaxDynamicSharedMemorySize, 2 * LSTG);
    cudaFuncSetAttribute(gemmw, cudaFuncAttributeMaxDynamicSharedMemorySize, 2 * GSTG);

    // prep1 (14848 blocks)
    k_prep1<<<14848, 256>>>(inputs, state, rW, vv, qW, kW, vW, oW);

    // query = inputs @ qW (rowmask) -> qh/ql + Acat_c (emode 2)
    gemmw<<<dim3(8, 8, 1), 256, 2 * GSTG>>>(inh, inl, qWh, qWl, nof, nobf, nobf,
        512, 512, 512, 512, 0, 0, 0, 0, 0, 0, 1, mask, nobias, 0, 0, 2);
    // keyval = concat @ [kW|vW] -> bkey + val (emode 3)
    gemmw<<<dim3(16, 16, 1), 256, 2 * GSTG>>>(conh, conl, kvWh, kvWl, nof, nobf, nobf,
        512, 1024, 1024, 512, 0, 0, 0, 0, 0, 0, 1, nomask, nobias, 0, 0, 3);

    // qv per-head -> Acat_p via trig rotate (emode 4)
    gemmw<<<dim3(8, 8, HH), 256, 2 * GSTG>>>(qh, ql, relh, rell, nof, nobf, nobf,
        512, 512, 512, 64,
        0, 64, 0, (long)UU * DDim, 0, 0, HH, nomask, pVrel, 512, 0, 4);

    // ubias from bkey (64 blocks)
    k_ubias<<<64, 256>>>(uW);

    // logits (128x128 tiles, proven config)
    k_logits_wmma<<<dim3(KVL / 128, TT / 128, 16), 256, 2 * LSTG>>>(mask, smask);

    // softmax: warp per row, 8 rows per block
    k_softmax<<<16 * TT / 8, 256>>>();

    // attended = weights @ value -> bf16 hi/lo (emode 1), causal K-truncation
    gemmw<<<dim3(1, 4, 16), 256, 2 * GSTG>>>(Wh, Wl, valh, vall, nof, atth, attl,
        KVL, 512, 512, KVL,
        (long)HH * TT * KVL, (long)TT * KVL,
        (long)KVL * 512, 64,
        (long)TT * 512, 64, HH, nomask, nobias, 0, 1, 1);

    // out = attended @ output_W (emode 0)
    gemmw<<<dim3(8, 8, 1), 256, 2 * GSTG>>>(atth, attl, oWh, oWl, out, nobf, nobf,
        512, 512, 512, 512, 0, 0, 0, 0, 0, 0, 1, nomask, nobias, 0, 0, 0);
}

// round 15
// speedup vs baseline: 1.1000x; 1.1000x over previous
#include <cuda_runtime.h>
#include <cuda_bf16.h>
#include <mma.h>
#include <math.h>

using namespace nvcuda;

#define BB 2
#define TT 512
#define MMs 512
#define DDim 512
#define HH 8
#define UU 64
#define KVL 1024
#define LARGE_BIAS 10000.0f

// ---------------- scratch ----------------
__device__ __align__(128) float g_vrel[HH * DDim];
__device__ __align__(128) float g_ubias[BB * HH * KVL];
__device__ __align__(128) float g_logits[16 * TT * KVL];
__device__ __align__(128) float2 g_qtrig[TT * DDim];
// bf16 hi/lo pools
__device__ __align__(128) __nv_bfloat16 g_inh[BB * TT * DDim], g_inl[BB * TT * DDim];
__device__ __align__(128) __nv_bfloat16 g_conh[BB * KVL * DDim], g_conl[BB * KVL * DDim];
__device__ __align__(128) __nv_bfloat16 g_qWh[512 * 512], g_qWl[512 * 512];
__device__ __align__(128) __nv_bfloat16 g_kvWh[512 * 1024], g_kvWl[512 * 1024];
__device__ __align__(128) __nv_bfloat16 g_oWh[512 * 512], g_oWl[512 * 512];
__device__ __align__(128) __nv_bfloat16 g_relh[512 * 512], g_rell[512 * 512];
__device__ __align__(128) __nv_bfloat16 g_qh[BB * TT * 512], g_ql[BB * TT * 512];
__device__ __align__(128) __nv_bfloat16 g_valh[BB * KVL * 512], g_vall[BB * KVL * 512];
__device__ __align__(128) __nv_bfloat16 g_atth[BB * TT * 512], g_attl[BB * TT * 512];
__device__ __align__(128) __nv_bfloat16 g_Wh[16 * TT * KVL], g_Wl[16 * TT * KVL];
__device__ __align__(128) __nv_bfloat16 g_Ktrig_h[KVL * 1024], g_Ktrig_l[KVL * 1024];
__device__ __align__(128) __nv_bfloat16 g_Bkey_h[16 * KVL * UU], g_Bkey_l[16 * KVL * UU];
__device__ __align__(128) __nv_bfloat16 g_Acat_h[16 * TT * 1088], g_Acat_l[16 * TT * 1088];

__device__ __forceinline__ void bsplit(float x, __nv_bfloat16& h, __nv_bfloat16& l) {
    h = __float2bfloat16(x);
    l = __float2bfloat16(x - __bfloat162float(h));
}
__device__ __forceinline__ void cpa16(void* sdst, const void* gsrc) {
    unsigned s = (unsigned)__cvta_generic_to_shared(sdst);
    asm volatile("cp.async.cg.shared.global [%0], [%1], 16;" :: "r"(s), "l"(gsrc));
}
#define CP_COMMIT() asm volatile("cp.async.commit_group;" ::: "memory")
#define CP_WAIT1()  asm volatile("cp.async.wait_group 1;" ::: "memory")
#define CP_WAIT0()  asm volatile("cp.async.wait_group 0;" ::: "memory")
__device__ __forceinline__ float ex2f(float x) {
    float r;
    asm("ex2.approx.ftz.f32 %0, %1;" : "=f"(r) : "f"(x));
    return r;
}

// ---------------- prep1 (14848 blocks) ----------------
__global__ void __launch_bounds__(256) k_prep1(
    const float* __restrict__ in, const float* __restrict__ st,
    const float* __restrict__ rW, const float* __restrict__ vv,
    const float* __restrict__ qW, const float* __restrict__ kW,
    const float* __restrict__ vW, const float* __restrict__ oW)
{
    int blk = blockIdx.x;
    int tid = threadIdx.x;
    if (blk < 4096) {
        int i = blk * 256 + tid;
        int d = i & 511, j = (i >> 9) & 1023, b = i >> 19;
        float v = (j < MMs) ? st[((size_t)(b * MMs + j)) * 512 + d]
                            : in[((size_t)(b * TT + (j - MMs))) * 512 + d];
        __nv_bfloat16 hi, lo; bsplit(v, hi, lo);
        g_conh[i] = hi; g_conl[i] = lo;
        return;
    }
    blk -= 4096;
    if (blk < 1024) {
        int i = blk * 256 + tid;
        __nv_bfloat16 hi, lo; bsplit(rW[i], hi, lo);
        size_t o = (size_t)(i & 511) * 512 + (i >> 9);
        g_relh[o] = hi; g_rell[o] = lo;
        return;
    }
    blk -= 1024;
    if (blk < 512) {
        int g = (blk * 256 + tid) >> 5, lane = tid & 31;
        int h = g >> 9, d = g & 511;
        const float* rp = rW + (size_t)d * 512 + h * 64;
        const float* vp = vv + h * 64;
        float s = rp[lane] * vp[lane] + rp[lane + 32] * vp[lane + 32];
#pragma unroll
        for (int o = 16; o > 0; o >>= 1) s += __shfl_xor_sync(~0u, s, o);
        if (!lane) g_vrel[h * 512 + d] = s;
        return;
    }
    blk -= 512;
    if (blk < 1024) {
        int i = blk * 256 + tid;
        int d = i & 511, qt = i >> 9;
        float invw = powf(10000.0f, -2.0f * (float)d / 512.0f);
        float off = (d & 1) ? 1.57079632679489662f : 0.0f;
        float s, c;
        sincosf((float)(qt + 512) * invw + off, &s, &c);
        g_qtrig[i] = make_float2(s, c);
        return;
    }
    blk -= 1024;
    if (blk < 2048) {
        int i = blk * 256 + tid;
        int d = i & 511, kv = i >> 9;
        float invw = powf(10000.0f, -2.0f * (float)d / 512.0f);
        float s, c;
        sincosf((float)kv * invw, &s, &c);
        __nv_bfloat16 ch, cl, sh, sl;
        bsplit(c, ch, cl); bsplit(s, sh, sl);
        __nv_bfloat162 vh, vl;
        vh.x = ch; vh.y = sh; vl.x = cl; vl.y = sl;
        *(__nv_bfloat162*)&g_Ktrig_h[(size_t)kv * 1024 + 2 * d] = vh;
        *(__nv_bfloat162*)&g_Ktrig_l[(size_t)kv * 1024 + 2 * d] = vl;
        return;
    }
    blk -= 2048;
    if (blk < 2048) {
        int i = blk * 256 + tid;
        __nv_bfloat16 hi, lo; bsplit(in[i], hi, lo);
        g_inh[i] = hi; g_inl[i] = lo;
        return;
    }
    blk -= 2048;
    if (blk < 1024) {
        int i = blk * 256 + tid;
        __nv_bfloat16 hi, lo; bsplit(qW[i], hi, lo);
        g_qWh[i] = hi; g_qWl[i] = lo;
        return;
    }
    blk -= 1024;
    if (blk < 2048) {
        int i = blk * 256 + tid;
        int d = i >> 10, c = i & 1023;
        float x = (c < 512) ? kW[d * 512 + c] : vW[d * 512 + (c - 512)];
        __nv_bfloat16 hi, lo; bsplit(x, hi, lo);
        g_kvWh[i] = hi; g_kvWl[i] = lo;
        return;
    }
    blk -= 2048;
    {
        int i = blk * 256 + tid;
        __nv_bfloat16 hi, lo; bsplit(oW[i], hi, lo);
        g_oWh[i] = hi; g_oWl[i] = lo;
    }
}

// ---------------- ubias from bkey (64 blocks) ----------------
__global__ void __launch_bounds__(256) k_ubias(const float* __restrict__ uW) {
    int i = blockIdx.x * 256 + threadIdx.x;
    int kv = i & 1023, bh = i >> 10;
    int h = bh & 7;
    const __nv_bfloat16* kh = g_Bkey_h + ((size_t)bh * 1024 + kv) * 64;
    const __nv_bfloat16* kl = g_Bkey_l + ((size_t)bh * 1024 + kv) * 64;
    const float* up = uW + h * 64;
    float s = 0.f;
#pragma unroll
    for (int u = 0; u < 64; u++)
        s = fmaf(__bfloat162float(kh[u]) + __bfloat162float(kl[u]), up[u], s);
    g_ubias[i] = s;
}

// ---------------- WMMA hi/lo GEMM, templated epilogue ----------------
// EMODE: 0=fp32 C | 1=bf16 Chh/Cll | 2=query(qh/ql+Acat_c) | 3=keyval(bkey+val) | 4=qv(trig->Acat_p)
#define PADA 40
#define PADB 72
#define OUTLD 20
#define GA 10240
#define GB 4608
#define GSTG (2 * GA + 2 * GB)

template <int EMODE>
__global__ void __launch_bounds__(256) gemmw(
    const __nv_bfloat16* __restrict__ Ah, const __nv_bfloat16* __restrict__ Al,
    const __nv_bfloat16* __restrict__ Bh, const __nv_bfloat16* __restrict__ Bl,
    float* __restrict__ C,
    __nv_bfloat16* __restrict__ Chh, __nv_bfloat16* __restrict__ Cll,
    int lda, int ldb, int ldc, int Kdim,
    long az1, long az2, long bz1, long bz2, long cz1, long cz2, int Z2,
    const int* __restrict__ rowmask, const float* __restrict__ bias, long biasz2,
    int causal)
{
    extern __shared__ char dsm[];
    int z = blockIdx.z, z1 = z / Z2, z2 = z - z1 * Z2;
    const __nv_bfloat16* Ahp = Ah + (size_t)z1 * az1 + (size_t)z2 * az2;
    const __nv_bfloat16* Alp = Al + (size_t)z1 * az1 + (size_t)z2 * az2;
    const __nv_bfloat16* Bhp = Bh + (size_t)z1 * bz1 + (size_t)z2 * bz2;
    const __nv_bfloat16* Blp = Bl + (size_t)z1 * bz1 + (size_t)z2 * bz2;
    size_t coff = (size_t)z1 * cz1 + (size_t)z2 * cz2;
    const float* biasp = bias ? (bias + (size_t)z2 * biasz2) : (const float*)0;

    int m0 = blockIdx.y * 128, n0 = blockIdx.x * 64;
    int tid = threadIdx.x, wid = tid >> 5, lane = tid & 31;
    int wy = wid >> 1, wx = wid & 1;

    wmma::fragment<wmma::accumulator, 16, 16, 16, float> acc[2][2];
#pragma unroll
    for (int mi = 0; mi < 2; mi++)
#pragma unroll
        for (int ni = 0; ni < 2; ni++) wmma::fill_fragment(acc[mi][ni], 0.f);

    int Klim = Kdim;
    if (causal) {
        int km = m0 + 640;
        Klim = (km < Kdim) ? ((km + 31) & ~31) : Kdim;
    }
    int nCh = Klim >> 5;

    auto issue = [&](int c, int s) {
        int kc = c * 32;
        char* base = dsm + s * GSTG;
#pragma unroll
        for (int t = tid; t < 512; t += 256) {
            int row = t >> 2, seg = (t & 3) * 8;
            size_t go = (size_t)(m0 + row) * lda + kc + seg;
            size_t so = ((size_t)row * PADA + seg) * 2;
            cpa16(base + so, Ahp + go);
            cpa16(base + GA + so, Alp + go);
        }
        {
            int row = tid >> 3, seg = (tid & 7) * 8;
            size_t go = (size_t)(kc + row) * ldb + n0 + seg;
            size_t so = ((size_t)row * PADB + seg) * 2;
            cpa16(base + 2 * GA + so, Bhp + go);
            cpa16(base + 2 * GA + GB + so, Blp + go);
        }
        CP_COMMIT();
    };

    issue(0, 0);
    for (int c = 0; c < nCh; c++) {
        if (c + 1 < nCh) { issue(c + 1, (c + 1) & 1); CP_WAIT1(); }
        else             { CP_WAIT0(); }
        __syncthreads();
        char* base = dsm + (c & 1) * GSTG;
        __nv_bfloat16* sAh = (__nv_bfloat16*)base;
        __nv_bfloat16* sAl = (__nv_bfloat16*)(base + GA);
        __nv_bfloat16* sBh = (__nv_bfloat16*)(base + 2 * GA);
        __nv_bfloat16* sBl = (__nv_bfloat16*)(base + 2 * GA + GB);
#pragma unroll
        for (int ks = 0; ks < 2; ks++) {
            wmma::fragment<wmma::matrix_a, 16, 16, 16, __nv_bfloat16, wmma::row_major> fah[2], fal[2];
            wmma::fragment<wmma::matrix_b, 16, 16, 16, __nv_bfloat16, wmma::row_major> fbh[2], fbl[2];
#pragma unroll
            for (int mi = 0; mi < 2; mi++) {
                wmma::load_matrix_sync(fah[mi], &sAh[(wy * 32 + mi * 16) * PADA + ks * 16], PADA);
                wmma::load_matrix_sync(fal[mi], &sAl[(wy * 32 + mi * 16) * PADA + ks * 16], PADA);
            }
#pragma unroll
            for (int ni = 0; ni < 2; ni++) {
                wmma::load_matrix_sync(fbh[ni], &sBh[ks * 16 * PADB + wx * 32 + ni * 16], PADB);
                wmma::load_matrix_sync(fbl[ni], &sBl[ks * 16 * PADB + wx * 32 + ni * 16], PADB);
            }
#pragma unroll
            for (int mi = 0; mi < 2; mi++)
#pragma unroll
                for (int ni = 0; ni < 2; ni++) {
                    wmma::mma_sync(acc[mi][ni], fah[mi], fbh[ni], acc[mi][ni]);
                    wmma::mma_sync(acc[mi][ni], fah[mi], fbl[ni], acc[mi][ni]);
                    wmma::mma_sync(acc[mi][ni], fal[mi], fbh[ni], acc[mi][ni]);
                }
        }
        __syncthreads();
    }

    float* sOut = (float*)dsm + wid * 16 * OUTLD;
#pragma unroll
    for (int mi = 0; mi < 2; mi++)
#pragma unroll
        for (int ni = 0; ni < 2; ni++) {
            wmma::store_matrix_sync(sOut, acc[mi][ni], OUTLD, wmma::mem_row_major);
            __syncwarp();
#pragma unroll
            for (int e = 0; e < 8; e++) {
                int idx = lane * 8 + e;
                int r = idx >> 4, cc = idx & 15;
                int mg = m0 + wy * 32 + mi * 16 + r;
                int ng = n0 + wx * 32 + ni * 16 + cc;
                float x = sOut[r * OUTLD + cc];
                if (biasp) x += biasp[ng];
                if (rowmask) x *= rowmask[mg] ? 1.f : 0.f;
                size_t oi = coff + (size_t)mg * ldc + ng;
                if (EMODE == 0) {
                    C[oi] = x;
                } else if (EMODE == 1) {
                    __nv_bfloat16 hi, lo; bsplit(x, hi, lo);
                    Chh[oi] = hi; Cll[oi] = lo;
                } else if (EMODE == 2) {          // query -> qh/ql + Acat_c
                    __nv_bfloat16 hi, lo; bsplit(x, hi, lo);
                    g_qh[oi] = hi; g_ql[oi] = lo;
                    int b = mg >> 9, qt = mg & 511, h = ng >> 6, u = ng & 63;
                    size_t o2 = ((size_t)(b * 8 + h) * 512 + qt) * 1088 + u;
                    g_Acat_h[o2] = hi; g_Acat_l[o2] = lo;
                } else if (EMODE == 3) {          // keyval -> bkey / val
                    int b = mg >> 10, kv = mg & 1023;
                    __nv_bfloat16 hi, lo; bsplit(x, hi, lo);
                    if (ng < 512) {
                        int h = ng >> 6, u = ng & 63;
                        size_t o2 = ((size_t)(b * 8 + h) * 1024 + kv) * 64 + u;
                        g_Bkey_h[o2] = hi; g_Bkey_l[o2] = lo;
                    } else {
                        size_t o2 = (size_t)mg * 512 + (ng - 512);
                        g_valh[o2] = hi; g_vall[o2] = lo;
                    }
                } else {                          // 4: qv -> Acat_p (trig rotate)
                    int b = mg >> 9, qt = mg & 511;
                    float2 tr = g_qtrig[qt * 512 + ng];
                    __nv_bfloat16 sh, sl, ch2, cl2;
                    bsplit(x * tr.x, sh, sl);
                    bsplit(-x * tr.y, ch2, cl2);
                    size_t o2 = ((size_t)(b * 8 + z2) * 512 + qt) * 1088 + 64 + 2 * ng;
                    __nv_bfloat162 vh, vl;
                    vh.x = sh; vh.y = ch2; vl.x = sl; vl.y = cl2;
                    *(__nv_bfloat162*)&g_Acat_h[o2] = vh;
                    *(__nv_bfloat162*)&g_Acat_l[o2] = vl;
                }
            }
            __syncwarp();
        }
}

// ---------------- WMMA logits (proven 128x128, 2-stage cp.async) ----------------
#define LTILE 10240
#define LSTG  (4 * LTILE)

__global__ void __launch_bounds__(256, 1) k_logits_wmma(
    const int* __restrict__ qmask, const int* __restrict__ smask)
{
    extern __shared__ char dsm[];
    int tid = threadIdx.x, wid = tid >> 5, lane = tid & 31;
    int kv0 = blockIdx.x * 128, qt0 = blockIdx.y * 128, bh = blockIdx.z;
    int b = bh >> 3;

    if (kv0 >= qt0 + 640) {
        float4 neg = make_float4(-LARGE_BIAS, -LARGE_BIAS, -LARGE_BIAS, -LARGE_BIAS);
        for (int t = tid; t < 128 * 32; t += 256) {
            int r = t >> 5, c = (t & 31) * 4;
            *(float4*)&g_logits[((size_t)bh * TT + qt0 + r) * KVL + kv0 + c] = neg;
        }
        return;
    }

    int wy = wid >> 2, wx = wid & 3;
    wmma::fragment<wmma::accumulator, 16, 16, 16, float> acc[4][2];
#pragma unroll
    for (int mi = 0; mi < 4; mi++)
#pragma unroll
        for (int ni = 0; ni < 2; ni++) wmma::fill_fragment(acc[mi][ni], 0.f);

    const __nv_bfloat16* Ah = g_Acat_h + ((size_t)bh * TT + qt0) * 1088;
    const __nv_bfloat16* Al = g_Acat_l + ((size_t)bh * TT + qt0) * 1088;
    const __nv_bfloat16* BKh = g_Bkey_h + (size_t)bh * KVL * 64;
    const __nv_bfloat16* BKl = g_Bkey_l + (size_t)bh * KVL * 64;

    auto issue = [&](int kc, int s) {
        const __nv_bfloat16 *Bhp, *Blp;
        size_t bld;
        int bcol;
        if (kc < 2) { Bhp = BKh; Blp = BKl; bld = 64; bcol = kc * 32; }
        else        { Bhp = g_Ktrig_h; Blp = g_Ktrig_l; bld = 1024; bcol = (kc - 2) * 32; }
        char* base = dsm + s * LSTG;
#pragma unroll
        for (int t = tid; t < 512; t += 256) {
            int row = t >> 2, seg = (t & 3) * 8;
            size_t so = ((size_t)row * PADA + seg) * 2;
            cpa16(base + so,             Ah + (size_t)row * 1088 + kc * 32 + seg);
            cpa16(base + LTILE + so,     Al + (size_t)row * 1088 + kc * 32 + seg);
            cpa16(base + 2 * LTILE + so, Bhp + (size_t)(kv0 + row) * bld + bcol + seg);
            cpa16(base + 3 * LTILE + so, Blp + (size_t)(kv0 + row) * bld + bcol + seg);
        }
        CP_COMMIT();
    };

    issue(0, 0);
    for (int kc = 0; kc < 34; kc++) {
        if (kc + 1 < 34) { issue(kc + 1, (kc + 1) & 1); CP_WAIT1(); }
        else             { CP_WAIT0(); }
        __syncthreads();
        char* base = dsm + (kc & 1) * LSTG;
        __nv_bfloat16* sAh = (__nv_bfloat16*)base;
        __nv_bfloat16* sAl = (__nv_bfloat16*)(base + LTILE);
        __nv_bfloat16* sBh = (__nv_bfloat16*)(base + 2 * LTILE);
        __nv_bfloat16* sBl = (__nv_bfloat16*)(base + 3 * LTILE);
#pragma unroll
        for (int ks = 0; ks < 2; ks++) {
            wmma::fragment<wmma::matrix_b, 16, 16, 16, __nv_bfloat16, wmma::col_major> fbh[2], fbl[2];
#pragma unroll
            for (int ni = 0; ni < 2; ni++) {
                wmma::load_matrix_sync(fbh[ni], &sBh[(wx * 32 + ni * 16) * PADA + ks * 16], PADA);
                wmma::load_matrix_sync(fbl[ni], &sBl[(wx * 32 + ni * 16) * PADA + ks * 16], PADA);
            }
#pragma unroll
            for (int mi = 0; mi < 4; mi++) {
                wmma::fragment<wmma::matrix_a, 16, 16, 16, __nv_bfloat16, wmma::row_major> fah, fal;
                wmma::load_matrix_sync(fah, &sAh[(wy * 64 + mi * 16) * PADA + ks * 16], PADA);
                wmma::load_matrix_sync(fal, &sAl[(wy * 64 + mi * 16) * PADA + ks * 16], PADA);
#pragma unroll
                for (int ni = 0; ni < 2; ni++) {
                    wmma::mma_sync(acc[mi][ni], fah, fbh[ni], acc[mi][ni]);
                    wmma::mma_sync(acc[mi][ni], fah, fbl[ni], acc[mi][ni]);
                    wmma::mma_sync(acc[mi][ni], fal, fbh[ni], acc[mi][ni]);
                }
            }
        }
        __syncthreads();
    }

    float* sOut = (float*)dsm + wid * 16 * OUTLD;
    const float* ub = g_ubias + (size_t)bh * KVL;
#pragma unroll
    for (int mi = 0; mi < 4; mi++)
#pragma unroll
        for (int ni = 0; ni < 2; ni++) {
            wmma::store_matrix_sync(sOut, acc[mi][ni], OUTLD, wmma::mem_row_major);
            __syncwarp();
#pragma unroll
            for (int e = 0; e < 8; e++) {
                int idx = lane * 8 + e;
                int r = idx >> 4, c = idx & 15;
                int qt = qt0 + wy * 64 + mi * 16 + r;
                int kv = kv0 + wx * 32 + ni * 16 + c;
                float x = (sOut[r * OUTLD + c] + ub[kv]) * 0.125f;
                if (kv - qt >= 513) x -= LARGE_BIAS;
                int cm = (kv < MMs) ? smask[b * MMs + kv] : qmask[b * TT + (kv - MMs)];
                if (!cm) x -= LARGE_BIAS;
                g_logits[((size_t)bh * TT + qt) * KVL + kv] = x;
            }
            __syncwarp();
        }
}

// ---------------- softmax: warp-per-row -> bf16 hi/lo weights ----------------
__global__ void __launch_bounds__(256) k_softmax() {
    int wid = threadIdx.x >> 5, lane = threadIdx.x & 31;
    size_t ro = ((size_t)blockIdx.x * 8 + wid) * KVL;
    const float* row = g_logits + ro;

    float4 v[8];
#pragma unroll
    for (int i = 0; i < 8; i++) v[i] = *(const float4*)&row[i * 128 + lane * 4];

    float mx = -1e30f;
#pragma unroll
    for (int i = 0; i < 8; i++)
        mx = fmaxf(mx, fmaxf(fmaxf(v[i].x, v[i].y), fmaxf(v[i].z, v[i].w)));
#pragma unroll
    for (int o = 16; o > 0; o >>= 1) mx = fmaxf(mx, __shfl_xor_sync(~0u, mx, o));

    float s = 0.f;
#pragma unroll
    for (int i = 0; i < 8; i++) {
        v[i].x = ex2f((v[i].x - mx) * 1.44269504f);
        v[i].y = ex2f((v[i].y - mx) * 1.44269504f);
        v[i].z = ex2f((v[i].z - mx) * 1.44269504f);
        v[i].w = ex2f((v[i].w - mx) * 1.44269504f);
        s += v[i].x + v[i].y + v[i].z + v[i].w;
    }
#pragma unroll
    for (int o = 16; o > 0; o >>= 1) s += __shfl_xor_sync(~0u, s, o);
    float inv = 1.f / s;

#pragma unroll
    for (int i = 0; i < 8; i++) {
        float w0 = v[i].x * inv, w1 = v[i].y * inv, w2 = v[i].z * inv, w3 = v[i].w * inv;
        __nv_bfloat16 h0, l0, h1, l1, h2, l2, h3, l3;
        bsplit(w0, h0, l0); bsplit(w1, h1, l1);
        bsplit(w2, h2, l2); bsplit(w3, h3, l3);
        __nv_bfloat162 ph0, ph1, pl0, pl1;
        ph0.x = h0; ph0.y = h1; ph1.x = h2; ph1.y = h3;
        pl0.x = l0; pl0.y = l1; pl1.x = l2; pl1.y = l3;
        size_t o = ro + i * 128 + lane * 4;
        *(__nv_bfloat162*)&g_Wh[o] = ph0;
        *(__nv_bfloat162*)&g_Wh[o + 2] = ph1;
        *(__nv_bfloat162*)&g_Wl[o] = pl0;
        *(__nv_bfloat162*)&g_Wl[o + 2] = pl1;
    }
}

// ---------------- host ----------------
static float* symaddr(const void* s) { void* p = 0; cudaGetSymbolAddress(&p, s); return (float*)p; }
static __nv_bfloat16* symaddrb(const void* s) { void* p = 0; cudaGetSymbolAddress(&p, s); return (__nv_bfloat16*)p; }

extern "C" void kernel_launch(void* const* d_in, const int* in_sizes, int n_in,
                              void* d_out, int out_size) {
    (void)in_sizes; (void)n_in; (void)out_size;
    const float* inputs = (const float*)d_in[0];
    const float* state  = (const float*)d_in[1];
    const int* mask     = (const int*)d_in[2];
    const int* smask    = (const int*)d_in[3];
    const float* qW = (const float*)d_in[4];
    const float* kW = (const float*)d_in[5];
    const float* rW = (const float*)d_in[6];
    const float* vW = (const float*)d_in[7];
    const float* uW = (const float*)d_in[8];
    const float* vv = (const float*)d_in[9];
    const float* oW = (const float*)d_in[10];
    float* out = (float*)d_out;

    float* pVrel = symaddr(g_vrel);

    __nv_bfloat16 *inh = symaddrb(g_inh), *inl = symaddrb(g_inl);
    __nv_bfloat16 *conh = symaddrb(g_conh), *conl = symaddrb(g_conl);
    __nv_bfloat16 *qWh = symaddrb(g_qWh), *qWl = symaddrb(g_qWl);
    __nv_bfloat16 *kvWh = symaddrb(g_kvWh), *kvWl = symaddrb(g_kvWl);
    __nv_bfloat16 *oWh = symaddrb(g_oWh), *oWl = symaddrb(g_oWl);
    __nv_bfloat16 *relh = symaddrb(g_relh), *rell = symaddrb(g_rell);
    __nv_bfloat16 *qh = symaddrb(g_qh), *ql = symaddrb(g_ql);
    __nv_bfloat16 *valh = symaddrb(g_valh), *vall = symaddrb(g_vall);
    __nv_bfloat16 *atth = symaddrb(g_atth), *attl = symaddrb(g_attl);
    __nv_bfloat16 *Wh = symaddrb(g_Wh), *Wl = symaddrb(g_Wl);

    const int* nomask = (const int*)0;
    const float* nobias = (const float*)0;
    __nv_bfloat16* nobf = (__nv_bfloat16*)0;
    float* nof = (float*)0;

    cudaFuncSetAttribute(k_logits_wmma, cudaFuncAttributeMaxDynamicSharedMemorySize, 2 * LSTG);
    cudaFuncSetAttribute(gemmw<0>, cudaFuncAttributeMaxDynamicSharedMemorySize, 2 * GSTG);
    cudaFuncSetAttribute(gemmw<1>, cudaFuncAttributeMaxDynamicSharedMemorySize, 2 * GSTG);
    cudaFuncSetAttribute(gemmw<2>, cudaFuncAttributeMaxDynamicSharedMemorySize, 2 * GSTG);
    cudaFuncSetAttribute(gemmw<3>, cudaFuncAttributeMaxDynamicSharedMemorySize, 2 * GSTG);
    cudaFuncSetAttribute(gemmw<4>, cudaFuncAttributeMaxDynamicSharedMemorySize, 2 * GSTG);

    // prep1 (14848 blocks)
    k_prep1<<<14848, 256>>>(inputs, state, rW, vv, qW, kW, vW, oW);

    // query = inputs @ qW (rowmask) -> qh/ql + Acat_c
    gemmw<2><<<dim3(8, 8, 1), 256, 2 * GSTG>>>(inh, inl, qWh, qWl, nof, nobf, nobf,
        512, 512, 512, 512, 0, 0, 0, 0, 0, 0, 1, mask, nobias, 0, 0);
    // keyval = concat @ [kW|vW] -> bkey + val
    gemmw<3><<<dim3(16, 16, 1), 256, 2 * GSTG>>>(conh, conl, kvWh, kvWl, nof, nobf, nobf,
        512, 1024, 1024, 512, 0, 0, 0, 0, 0, 0, 1, nomask, nobias, 0, 0);

    // qv per-head -> Acat_p via trig rotate
    gemmw<4><<<dim3(8, 8, HH), 256, 2 * GSTG>>>(qh, ql, relh, rell, nof, nobf, nobf,
        512, 512, 512, 64,
        0, 64, 0, (long)UU * DDim, 0, 0, HH, nomask, pVrel, 512, 0);

    // ubias from bkey
    k_ubias<<<64, 256>>>(uW);

    // logits (128x128 tiles, proven config)
    k_logits_wmma<<<dim3(KVL / 128, TT / 128, 16), 256, 2 * LSTG>>>(mask, smask);

    // softmax: warp per row
    k_softmax<<<16 * TT / 8, 256>>>();

    // attended = weights @ value -> bf16 hi/lo, causal K-truncation
    gemmw<1><<<dim3(1, 4, 16), 256, 2 * GSTG>>>(Wh, Wl, valh, vall, nof, atth, attl,
        KVL, 512, 512, KVL,
        (long)HH * TT * KVL, (long)TT * KVL,
        (long)KVL * 512, 64,
        (long)TT * 512, 64, HH, nomask, nobias, 0, 1);

    // out = attended @ output_W
    gemmw<0><<<dim3(8, 8, 1), 256, 2 * GSTG>>>(atth, attl, oWh, oWl, out, nobf, nobf,
        512, 512, 512, 512, 0, 0, 0, 0, 0, 0, 1, nomask, nobias, 0, 0);
}

// round 16
// speedup vs baseline: 1.1942x; 1.0857x over previous
#include <cuda_runtime.h>
#include <cuda_bf16.h>
#include <mma.h>
#include <math.h>

using namespace nvcuda;

#define BB 2
#define TT 512
#define MMs 512
#define DDim 512
#define HH 8
#define UU 64
#define KVL 1024
#define LARGE_BIAS 10000.0f
#define INVW_C (-0.05190512648f)   // -2/512 * log2(10000)

// ---------------- scratch ----------------
__device__ __align__(128) float g_query[BB * TT * 512];
__device__ __align__(128) float g_keyval[BB * KVL * 1024];
__device__ __align__(128) float g_vrel[HH * DDim];
__device__ __align__(128) float g_qv[BB * TT * HH * DDim];
__device__ __align__(128) float g_ubias[BB * HH * KVL];
__device__ __align__(128) float g_logits[16 * TT * KVL];
__device__ __align__(128) float g_att[BB * TT * 512];
__device__ __align__(128) float2 g_qtrig[TT * DDim];
// bf16 hi/lo pools
__device__ __align__(128) __nv_bfloat16 g_inh[BB * TT * DDim], g_inl[BB * TT * DDim];
__device__ __align__(128) __nv_bfloat16 g_conh[BB * KVL * DDim], g_conl[BB * KVL * DDim];
__device__ __align__(128) __nv_bfloat16 g_qWh[512 * 512], g_qWl[512 * 512];
__device__ __align__(128) __nv_bfloat16 g_kvWh[512 * 1024], g_kvWl[512 * 1024];
__device__ __align__(128) __nv_bfloat16 g_oWh[512 * 512], g_oWl[512 * 512];
__device__ __align__(128) __nv_bfloat16 g_relh[512 * 512], g_rell[512 * 512];
__device__ __align__(128) __nv_bfloat16 g_qh[BB * TT * 512], g_ql[BB * TT * 512];
__device__ __align__(128) __nv_bfloat16 g_valh[BB * KVL * 512], g_vall[BB * KVL * 512];
__device__ __align__(128) __nv_bfloat16 g_atth[BB * TT * 512], g_attl[BB * TT * 512];
__device__ __align__(128) __nv_bfloat16 g_Wh[16 * TT * KVL], g_Wl[16 * TT * KVL];
__device__ __align__(128) __nv_bfloat16 g_Ktrig_h[KVL * 1024], g_Ktrig_l[KVL * 1024];
__device__ __align__(128) __nv_bfloat16 g_Bkey_h[16 * KVL * UU], g_Bkey_l[16 * KVL * UU];
__device__ __align__(128) __nv_bfloat16 g_Acat_h[16 * TT * 1088], g_Acat_l[16 * TT * 1088];

__device__ __forceinline__ void bsplit(float x, __nv_bfloat16& h, __nv_bfloat16& l) {
    h = __float2bfloat16(x);
    l = __float2bfloat16(x - __bfloat162float(h));
}
__device__ __forceinline__ void cpa16(void* sdst, const void* gsrc) {
    unsigned s = (unsigned)__cvta_generic_to_shared(sdst);
    asm volatile("cp.async.cg.shared.global [%0], [%1], 16;" :: "r"(s), "l"(gsrc));
}
#define CP_COMMIT() asm volatile("cp.async.commit_group;" ::: "memory")
#define CP_WAIT1()  asm volatile("cp.async.wait_group 1;" ::: "memory")
#define CP_WAIT0()  asm volatile("cp.async.wait_group 0;" ::: "memory")
__device__ __forceinline__ float ex2f(float x) {
    float r;
    asm("ex2.approx.ftz.f32 %0, %1;" : "=f"(r) : "f"(x));
    return r;
}

// ---------------- prep1 (14848 blocks) ----------------
__global__ void __launch_bounds__(256) k_prep1(
    const float* __restrict__ in, const float* __restrict__ st,
    const float* __restrict__ rW, const float* __restrict__ vv,
    const float* __restrict__ qW, const float* __restrict__ kW,
    const float* __restrict__ vW, const float* __restrict__ oW)
{
    int blk = blockIdx.x;
    int tid = threadIdx.x;
    if (blk < 4096) {
        int i = blk * 256 + tid;
        int d = i & 511, j = (i >> 9) & 1023, b = i >> 19;
        float v = (j < MMs) ? st[((size_t)(b * MMs + j)) * 512 + d]
                            : in[((size_t)(b * TT + (j - MMs))) * 512 + d];
        __nv_bfloat16 hi, lo; bsplit(v, hi, lo);
        g_conh[i] = hi; g_conl[i] = lo;
        return;
    }
    blk -= 4096;
    if (blk < 1024) {
        int i = blk * 256 + tid;
        __nv_bfloat16 hi, lo; bsplit(rW[i], hi, lo);
        size_t o = (size_t)(i & 511) * 512 + (i >> 9);
        g_relh[o] = hi; g_rell[o] = lo;
        return;
    }
    blk -= 1024;
    if (blk < 512) {
        int g = (blk * 256 + tid) >> 5, lane = tid & 31;
        int h = g >> 9, d = g & 511;
        const float* rp = rW + (size_t)d * 512 + h * 64;
        const float* vp = vv + h * 64;
        float s = rp[lane] * vp[lane] + rp[lane + 32] * vp[lane + 32];
#pragma unroll
        for (int o = 16; o > 0; o >>= 1) s += __shfl_xor_sync(~0u, s, o);
        if (!lane) g_vrel[h * 512 + d] = s;
        return;
    }
    blk -= 512;
    if (blk < 1024) {
        int i = blk * 256 + tid;
        int d = i & 511, qt = i >> 9;
        float invw = exp2f((float)d * INVW_C);
        float off = (d & 1) ? 1.57079632679489662f : 0.0f;
        float s, c;
        sincosf((float)(qt + 512) * invw + off, &s, &c);
        g_qtrig[i] = make_float2(s, c);
        return;
    }
    blk -= 1024;
    if (blk < 2048) {
        int i = blk * 256 + tid;
        int d = i & 511, kv = i >> 9;
        float invw = exp2f((float)d * INVW_C);
        float s, c;
        sincosf((float)kv * invw, &s, &c);
        __nv_bfloat16 ch, cl, sh, sl;
        bsplit(c, ch, cl); bsplit(s, sh, sl);
        __nv_bfloat162 vh, vl;
        vh.x = ch; vh.y = sh; vl.x = cl; vl.y = sl;
        *(__nv_bfloat162*)&g_Ktrig_h[(size_t)kv * 1024 + 2 * d] = vh;
        *(__nv_bfloat162*)&g_Ktrig_l[(size_t)kv * 1024 + 2 * d] = vl;
        return;
    }
    blk -= 2048;
    if (blk < 2048) {
        int i = blk * 256 + tid;
        __nv_bfloat16 hi, lo; bsplit(in[i], hi, lo);
        g_inh[i] = hi; g_inl[i] = lo;
        return;
    }
    blk -= 2048;
    if (blk < 1024) {
        int i = blk * 256 + tid;
        __nv_bfloat16 hi, lo; bsplit(qW[i], hi, lo);
        g_qWh[i] = hi; g_qWl[i] = lo;
        return;
    }
    blk -= 1024;
    if (blk < 2048) {
        int i = blk * 256 + tid;
        int d = i >> 10, c = i & 1023;
        float x = (c < 512) ? kW[d * 512 + c] : vW[d * 512 + (c - 512)];
        __nv_bfloat16 hi, lo; bsplit(x, hi, lo);
        g_kvWh[i] = hi; g_kvWl[i] = lo;
        return;
    }
    blk -= 2048;
    {
        int i = blk * 256 + tid;
        __nv_bfloat16 hi, lo; bsplit(oW[i], hi, lo);
        g_oWh[i] = hi; g_oWl[i] = lo;
    }
}

// ---------------- prep2 (12352 blocks) ----------------
__global__ void __launch_bounds__(256) k_prep2(const float* __restrict__ uW) {
    int blk = blockIdx.x;
    int tid = threadIdx.x;
    if (blk < 2048) {
        int i = blk * 256 + tid;
        __nv_bfloat16 hi, lo; bsplit(g_query[i], hi, lo);
        g_qh[i] = hi; g_ql[i] = lo;
        return;
    }
    blk -= 2048;
    if (blk < 4096) {
        int i = blk * 256 + tid;
        int c = i & 511, row = i >> 9;
        __nv_bfloat16 hi, lo;
        bsplit(g_keyval[(size_t)row * 1024 + 512 + c], hi, lo);
        g_valh[i] = hi; g_vall[i] = lo;
        return;
    }
    blk -= 4096;
    if (blk < 64) {
        int i = blk * 256 + tid;
        int kv = i & 1023, h = (i >> 10) & 7, b = i >> 13;
        const float* kp = g_keyval + ((size_t)(b * KVL + kv)) * 1024 + h * 64;
        const float* up = uW + h * 64;
        float s = 0.f;
#pragma unroll
        for (int u = 0; u < 64; u++) s = fmaf(kp[u], up[u], s);
        g_ubias[i] = s;
        return;
    }
    blk -= 64;
    if (blk < 4096) {
        int i = blk * 256 + tid;
        int u = i & 63, kv = (i >> 6) & 1023, bh = i >> 16;
        int b = bh >> 3, h = bh & 7;
        __nv_bfloat16 hi, lo;
        bsplit(g_keyval[(size_t)(b * KVL + kv) * 1024 + h * 64 + u], hi, lo);
        g_Bkey_h[i] = hi; g_Bkey_l[i] = lo;
        return;
    }
    blk -= 4096;
    {
        int i = blk * 256 + tid;
        int u = i & 63, qt = (i >> 6) & 511, bh = i >> 15;
        int b = bh >> 3, h = bh & 7;
        __nv_bfloat16 hi, lo;
        bsplit(g_query[(size_t)(b * TT + qt) * 512 + h * 64 + u], hi, lo);
        size_t o = ((size_t)bh * TT + qt) * 1088 + u;
        g_Acat_h[o] = hi; g_Acat_l[o] = lo;
    }
}

__global__ void k_acat_p() {
    int i = blockIdx.x * blockDim.x + threadIdx.x;
    if (i >= 16 * TT * DDim) return;
    int d = i & 511, qt = (i >> 9) & 511, bh = i >> 18;
    int b = bh >> 3, h = bh & 7;
    float q = g_qv[(size_t)(b * TT + qt) * 4096 + h * 512 + d];
    float2 tr = g_qtrig[qt * 512 + d];
    __nv_bfloat16 sh, sl, ch, cl;
    bsplit(q * tr.x, sh, sl);
    bsplit(-q * tr.y, ch, cl);
    size_t o = ((size_t)bh * TT + qt) * 1088 + 64 + 2 * d;
    __nv_bfloat162 vh, vl;
    vh.x = sh; vh.y = ch; vl.x = sl; vl.y = cl;
    *(__nv_bfloat162*)&g_Acat_h[o] = vh;
    *(__nv_bfloat162*)&g_Acat_l[o] = vl;
}

// ---------------- WMMA hi/lo GEMM, cp.async 2-stage pipelined ----------------
#define PADA 40
#define PADB 72
#define OUTLD 20
#define GA 10240
#define GB 4608
#define GSTG (2 * GA + 2 * GB)

__global__ void __launch_bounds__(256) gemmw(
    const __nv_bfloat16* __restrict__ Ah, const __nv_bfloat16* __restrict__ Al,
    const __nv_bfloat16* __restrict__ Bh, const __nv_bfloat16* __restrict__ Bl,
    float* __restrict__ C,
    __nv_bfloat16* __restrict__ Chh, __nv_bfloat16* __restrict__ Cll,
    int lda, int ldb, int ldc, int Kdim,
    long az1, long az2, long bz1, long bz2, long cz1, long cz2, int Z2,
    const int* __restrict__ rowmask, const float* __restrict__ bias, long biasz2,
    int causal)
{
    extern __shared__ char dsm[];
    int z = blockIdx.z, z1 = z / Z2, z2 = z - z1 * Z2;
    const __nv_bfloat16* Ahp = Ah + (size_t)z1 * az1 + (size_t)z2 * az2;
    const __nv_bfloat16* Alp = Al + (size_t)z1 * az1 + (size_t)z2 * az2;
    const __nv_bfloat16* Bhp = Bh + (size_t)z1 * bz1 + (size_t)z2 * bz2;
    const __nv_bfloat16* Blp = Bl + (size_t)z1 * bz1 + (size_t)z2 * bz2;
    size_t coff = (size_t)z1 * cz1 + (size_t)z2 * cz2;
    const float* biasp = bias ? (bias + (size_t)z2 * biasz2) : (const float*)0;

    int m0 = blockIdx.y * 128, n0 = blockIdx.x * 64;
    int tid = threadIdx.x, wid = tid >> 5, lane = tid & 31;
    int wy = wid >> 1, wx = wid & 1;

    wmma::fragment<wmma::accumulator, 16, 16, 16, float> acc[2][2];
#pragma unroll
    for (int mi = 0; mi < 2; mi++)
#pragma unroll
        for (int ni = 0; ni < 2; ni++) wmma::fill_fragment(acc[mi][ni], 0.f);

    int Klim = Kdim;
    if (causal) {
        int km = m0 + 640;
        Klim = (km < Kdim) ? ((km + 31) & ~31) : Kdim;
    }
    int nCh = Klim >> 5;

    auto issue = [&](int c, int s) {
        int kc = c * 32;
        char* base = dsm + s * GSTG;
#pragma unroll
        for (int t = tid; t < 512; t += 256) {
            int row = t >> 2, seg = (t & 3) * 8;
            size_t go = (size_t)(m0 + row) * lda + kc + seg;
            size_t so = ((size_t)row * PADA + seg) * 2;
            cpa16(base + so, Ahp + go);
            cpa16(base + GA + so, Alp + go);
        }
        {
            int row = tid >> 3, seg = (tid & 7) * 8;
            size_t go = (size_t)(kc + row) * ldb + n0 + seg;
            size_t so = ((size_t)row * PADB + seg) * 2;
            cpa16(base + 2 * GA + so, Bhp + go);
            cpa16(base + 2 * GA + GB + so, Blp + go);
        }
        CP_COMMIT();
    };

    issue(0, 0);
    for (int c = 0; c < nCh; c++) {
        if (c + 1 < nCh) { issue(c + 1, (c + 1) & 1); CP_WAIT1(); }
        else             { CP_WAIT0(); }
        __syncthreads();
        char* base = dsm + (c & 1) * GSTG;
        __nv_bfloat16* sAh = (__nv_bfloat16*)base;
        __nv_bfloat16* sAl = (__nv_bfloat16*)(base + GA);
        __nv_bfloat16* sBh = (__nv_bfloat16*)(base + 2 * GA);
        __nv_bfloat16* sBl = (__nv_bfloat16*)(base + 2 * GA + GB);
#pragma unroll
        for (int ks = 0; ks < 2; ks++) {
            wmma::fragment<wmma::matrix_a, 16, 16, 16, __nv_bfloat16, wmma::row_major> fah[2], fal[2];
            wmma::fragment<wmma::matrix_b, 16, 16, 16, __nv_bfloat16, wmma::row_major> fbh[2], fbl[2];
#pragma unroll
            for (int mi = 0; mi < 2; mi++) {
                wmma::load_matrix_sync(fah[mi], &sAh[(wy * 32 + mi * 16) * PADA + ks * 16], PADA);
                wmma::load_matrix_sync(fal[mi], &sAl[(wy * 32 + mi * 16) * PADA + ks * 16], PADA);
            }
#pragma unroll
            for (int ni = 0; ni < 2; ni++) {
                wmma::load_matrix_sync(fbh[ni], &sBh[ks * 16 * PADB + wx * 32 + ni * 16], PADB);
                wmma::load_matrix_sync(fbl[ni], &sBl[ks * 16 * PADB + wx * 32 + ni * 16], PADB);
            }
#pragma unroll
            for (int mi = 0; mi < 2; mi++)
#pragma unroll
                for (int ni = 0; ni < 2; ni++) {
                    wmma::mma_sync(acc[mi][ni], fah[mi], fbh[ni], acc[mi][ni]);
                    wmma::mma_sync(acc[mi][ni], fah[mi], fbl[ni], acc[mi][ni]);
                    wmma::mma_sync(acc[mi][ni], fal[mi], fbh[ni], acc[mi][ni]);
                }
        }
        __syncthreads();
    }

    float* sOut = (float*)dsm + wid * 16 * OUTLD;
#pragma unroll
    for (int mi = 0; mi < 2; mi++)
#pragma unroll
        for (int ni = 0; ni < 2; ni++) {
            wmma::store_matrix_sync(sOut, acc[mi][ni], OUTLD, wmma::mem_row_major);
            __syncwarp();
#pragma unroll
            for (int e = 0; e < 8; e++) {
                int idx = lane * 8 + e;
                int r = idx >> 4, cc = idx & 15;
                int mg = m0 + wy * 32 + mi * 16 + r;
                int ng = n0 + wx * 32 + ni * 16 + cc;
                float x = sOut[r * OUTLD + cc];
                if (biasp) x += biasp[ng];
                if (rowmask) x *= rowmask[mg] ? 1.f : 0.f;
                size_t oi = coff + (size_t)mg * ldc + ng;
                if (Chh) {
                    __nv_bfloat16 hi, lo;
                    bsplit(x, hi, lo);
                    Chh[oi] = hi; Cll[oi] = lo;
                } else {
                    C[oi] = x;
                }
            }
            __syncwarp();
        }
}

// ---------------- WMMA logits (proven 128x128, 2-stage cp.async) ----------------
#define LTILE 10240
#define LSTG  (4 * LTILE)

__global__ void __launch_bounds__(256, 1) k_logits_wmma(
    const int* __restrict__ qmask, const int* __restrict__ smask)
{
    extern __shared__ char dsm[];
    int tid = threadIdx.x, wid = tid >> 5, lane = tid & 31;
    int kv0 = blockIdx.x * 128, qt0 = blockIdx.y * 128, bh = blockIdx.z;
    int b = bh >> 3;

    if (kv0 >= qt0 + 640) {
        float4 neg = make_float4(-LARGE_BIAS, -LARGE_BIAS, -LARGE_BIAS, -LARGE_BIAS);
        for (int t = tid; t < 128 * 32; t += 256) {
            int r = t >> 5, c = (t & 31) * 4;
            *(float4*)&g_logits[((size_t)bh * TT + qt0 + r) * KVL + kv0 + c] = neg;
        }
        return;
    }

    int wy = wid >> 2, wx = wid & 3;
    wmma::fragment<wmma::accumulator, 16, 16, 16, float> acc[4][2];
#pragma unroll
    for (int mi = 0; mi < 4; mi++)
#pragma unroll
        for (int ni = 0; ni < 2; ni++) wmma::fill_fragment(acc[mi][ni], 0.f);

    const __nv_bfloat16* Ah = g_Acat_h + ((size_t)bh * TT + qt0) * 1088;
    const __nv_bfloat16* Al = g_Acat_l + ((size_t)bh * TT + qt0) * 1088;
    const __nv_bfloat16* BKh = g_Bkey_h + (size_t)bh * KVL * 64;
    const __nv_bfloat16* BKl = g_Bkey_l + (size_t)bh * KVL * 64;

    auto issue = [&](int kc, int s) {
        const __nv_bfloat16 *Bhp, *Blp;
        size_t bld;
        int bcol;
        if (kc < 2) { Bhp = BKh; Blp = BKl; bld = 64; bcol = kc * 32; }
        else        { Bhp = g_Ktrig_h; Blp = g_Ktrig_l; bld = 1024; bcol = (kc - 2) * 32; }
        char* base = dsm + s * LSTG;
#pragma unroll
        for (int t = tid; t < 512; t += 256) {
            int row = t >> 2, seg = (t & 3) * 8;
            size_t so = ((size_t)row * PADA + seg) * 2;
            cpa16(base + so,             Ah + (size_t)row * 1088 + kc * 32 + seg);
            cpa16(base + LTILE + so,     Al + (size_t)row * 1088 + kc * 32 + seg);
            cpa16(base + 2 * LTILE + so, Bhp + (size_t)(kv0 + row) * bld + bcol + seg);
            cpa16(base + 3 * LTILE + so, Blp + (size_t)(kv0 + row) * bld + bcol + seg);
        }
        CP_COMMIT();
    };

    issue(0, 0);
    for (int kc = 0; kc < 34; kc++) {
        if (kc + 1 < 34) { issue(kc + 1, (kc + 1) & 1); CP_WAIT1(); }
        else             { CP_WAIT0(); }
        __syncthreads();
        char* base = dsm + (kc & 1) * LSTG;
        __nv_bfloat16* sAh = (__nv_bfloat16*)base;
        __nv_bfloat16* sAl = (__nv_bfloat16*)(base + LTILE);
        __nv_bfloat16* sBh = (__nv_bfloat16*)(base + 2 * LTILE);
        __nv_bfloat16* sBl = (__nv_bfloat16*)(base + 3 * LTILE);
#pragma unroll
        for (int ks = 0; ks < 2; ks++) {
            wmma::fragment<wmma::matrix_b, 16, 16, 16, __nv_bfloat16, wmma::col_major> fbh[2], fbl[2];
#pragma unroll
            for (int ni = 0; ni < 2; ni++) {
                wmma::load_matrix_sync(fbh[ni], &sBh[(wx * 32 + ni * 16) * PADA + ks * 16], PADA);
                wmma::load_matrix_sync(fbl[ni], &sBl[(wx * 32 + ni * 16) * PADA + ks * 16], PADA);
            }
#pragma unroll
            for (int mi = 0; mi < 4; mi++) {
                wmma::fragment<wmma::matrix_a, 16, 16, 16, __nv_bfloat16, wmma::row_major> fah, fal;
                wmma::load_matrix_sync(fah, &sAh[(wy * 64 + mi * 16) * PADA + ks * 16], PADA);
                wmma::load_matrix_sync(fal, &sAl[(wy * 64 + mi * 16) * PADA + ks * 16], PADA);
#pragma unroll
                for (int ni = 0; ni < 2; ni++) {
                    wmma::mma_sync(acc[mi][ni], fah, fbh[ni], acc[mi][ni]);
                    wmma::mma_sync(acc[mi][ni], fah, fbl[ni], acc[mi][ni]);
                    wmma::mma_sync(acc[mi][ni], fal, fbh[ni], acc[mi][ni]);
                }
            }
        }
        __syncthreads();
    }

    float* sOut = (float*)dsm + wid * 16 * OUTLD;
    const float* ub = g_ubias + (size_t)bh * KVL;
#pragma unroll
    for (int mi = 0; mi < 4; mi++)
#pragma unroll
        for (int ni = 0; ni < 2; ni++) {
            wmma::store_matrix_sync(sOut, acc[mi][ni], OUTLD, wmma::mem_row_major);
            __syncwarp();
#pragma unroll
            for (int e = 0; e < 8; e++) {
                int idx = lane * 8 + e;
                int r = idx >> 4, c = idx & 15;
                int qt = qt0 + wy * 64 + mi * 16 + r;
                int kv = kv0 + wx * 32 + ni * 16 + c;
                float x = (sOut[r * OUTLD + c] + ub[kv]) * 0.125f;
                if (kv - qt >= 513) x -= LARGE_BIAS;
                int cm = (kv < MMs) ? smask[b * MMs + kv] : qmask[b * TT + (kv - MMs)];
                if (!cm) x -= LARGE_BIAS;
                g_logits[((size_t)bh * TT + qt) * KVL + kv] = x;
            }
            __syncwarp();
        }
}

// ---------------- softmax: warp-per-row, causal chunk-skip -> bf16 hi/lo weights ----------------
__global__ void __launch_bounds__(256) k_softmax() {
    int wid = threadIdx.x >> 5, lane = threadIdx.x & 31;
    int rrow = blockIdx.x * 8 + wid;
    int qt = rrow & 511;
    size_t ro = (size_t)rrow * KVL;
    const float* row = g_logits + ro;

    // chunks beyond qt+512 are causally dead (exp underflows to exactly 0)
    int nch = (qt + 512 + 128) >> 7;
    if (nch > 8) nch = 8;

    float4 v[8];
    float mx = -1e30f;
    for (int i = 0; i < nch; i++) {
        v[i] = *(const float4*)&row[i * 128 + lane * 4];
        mx = fmaxf(mx, fmaxf(fmaxf(v[i].x, v[i].y), fmaxf(v[i].z, v[i].w)));
    }
#pragma unroll
    for (int o = 16; o > 0; o >>= 1) mx = fmaxf(mx, __shfl_xor_sync(~0u, mx, o));

    float s = 0.f;
    for (int i = 0; i < nch; i++) {
        v[i].x = ex2f((v[i].x - mx) * 1.44269504f);
        v[i].y = ex2f((v[i].y - mx) * 1.44269504f);
        v[i].z = ex2f((v[i].z - mx) * 1.44269504f);
        v[i].w = ex2f((v[i].w - mx) * 1.44269504f);
        s += v[i].x + v[i].y + v[i].z + v[i].w;
    }
#pragma unroll
    for (int o = 16; o > 0; o >>= 1) s += __shfl_xor_sync(~0u, s, o);
    float inv = 1.f / s;

    for (int i = 0; i < nch; i++) {
        float w0 = v[i].x * inv, w1 = v[i].y * inv, w2 = v[i].z * inv, w3 = v[i].w * inv;
        __nv_bfloat16 h0, l0, h1, l1, h2, l2, h3, l3;
        bsplit(w0, h0, l0); bsplit(w1, h1, l1);
        bsplit(w2, h2, l2); bsplit(w3, h3, l3);
        __nv_bfloat162 ph0, ph1, pl0, pl1;
        ph0.x = h0; ph0.y = h1; ph1.x = h2; ph1.y = h3;
        pl0.x = l0; pl0.y = l1; pl1.x = l2; pl1.y = l3;
        size_t o = ro + i * 128 + lane * 4;
        *(__nv_bfloat162*)&g_Wh[o] = ph0;
        *(__nv_bfloat162*)&g_Wh[o + 2] = ph1;
        *(__nv_bfloat162*)&g_Wl[o] = pl0;
        *(__nv_bfloat162*)&g_Wl[o + 2] = pl1;
    }
    __nv_bfloat162 z2;
    z2.x = __float2bfloat16(0.f);
    z2.y = __float2bfloat16(0.f);
    for (int i = nch; i < 8; i++) {
        size_t o = ro + i * 128 + lane * 4;
        *(__nv_bfloat162*)&g_Wh[o] = z2;
        *(__nv_bfloat162*)&g_Wh[o + 2] = z2;
        *(__nv_bfloat162*)&g_Wl[o] = z2;
        *(__nv_bfloat162*)&g_Wl[o + 2] = z2;
    }
}

// ---------------- host ----------------
static float* symaddr(const void* s) { void* p = 0; cudaGetSymbolAddress(&p, s); return (float*)p; }
static __nv_bfloat16* symaddrb(const void* s) { void* p = 0; cudaGetSymbolAddress(&p, s); return (__nv_bfloat16*)p; }

extern "C" void kernel_launch(void* const* d_in, const int* in_sizes, int n_in,
                              void* d_out, int out_size) {
    (void)in_sizes; (void)n_in; (void)out_size;
    const float* inputs = (const float*)d_in[0];
    const float* state  = (const float*)d_in[1];
    const int* mask     = (const int*)d_in[2];
    const int* smask    = (const int*)d_in[3];
    const float* qW = (const float*)d_in[4];
    const float* kW = (const float*)d_in[5];
    const float* rW = (const float*)d_in[6];
    const float* vW = (const float*)d_in[7];
    const float* uW = (const float*)d_in[8];
    const float* vv = (const float*)d_in[9];
    const float* oW = (const float*)d_in[10];
    float* out = (float*)d_out;

    float* pQuery  = symaddr(g_query);
    float* pKeyVal = symaddr(g_keyval);
    float* pVrel   = symaddr(g_vrel);
    float* pQv     = symaddr(g_qv);
    float* pAtt    = symaddr(g_att);

    __nv_bfloat16 *inh = symaddrb(g_inh), *inl = symaddrb(g_inl);
    __nv_bfloat16 *conh = symaddrb(g_conh), *conl = symaddrb(g_conl);
    __nv_bfloat16 *qWh = symaddrb(g_qWh), *qWl = symaddrb(g_qWl);
    __nv_bfloat16 *kvWh = symaddrb(g_kvWh), *kvWl = symaddrb(g_kvWl);
    __nv_bfloat16 *oWh = symaddrb(g_oWh), *oWl = symaddrb(g_oWl);
    __nv_bfloat16 *relh = symaddrb(g_relh), *rell = symaddrb(g_rell);
    __nv_bfloat16 *qh = symaddrb(g_qh), *ql = symaddrb(g_ql);
    __nv_bfloat16 *valh = symaddrb(g_valh), *vall = symaddrb(g_vall);
    __nv_bfloat16 *atth = symaddrb(g_atth), *attl = symaddrb(g_attl);
    __nv_bfloat16 *Wh = symaddrb(g_Wh), *Wl = symaddrb(g_Wl);

    const int* nomask = (const int*)0;
    const float* nobias = (const float*)0;
    __nv_bfloat16* nobf = (__nv_bfloat16*)0;

    cudaFuncSetAttribute(k_logits_wmma, cudaFuncAttributeMaxDynamicSharedMemorySize, 2 * LSTG);
    cudaFuncSetAttribute(gemmw, cudaFuncAttributeMaxDynamicSharedMemorySize, 2 * GSTG);

    // prep1 (14848 blocks)
    k_prep1<<<14848, 256>>>(inputs, state, rW, vv, qW, kW, vW, oW);

    // query = inputs @ qW (rowmask)
    gemmw<<<dim3(8, 8, 1), 256, 2 * GSTG>>>(inh, inl, qWh, qWl, pQuery, nobf, nobf,
        512, 512, 512, 512, 0, 0, 0, 0, 0, 0, 1, mask, nobias, 0, 0);
    // keyval = concat @ [kW|vW]
    gemmw<<<dim3(16, 16, 1), 256, 2 * GSTG>>>(conh, conl, kvWh, kvWl, pKeyVal, nobf, nobf,
        512, 1024, 1024, 512, 0, 0, 0, 0, 0, 0, 1, nomask, nobias, 0, 0);

    // prep2 (12352 blocks)
    k_prep2<<<12352, 256>>>(uW);

    // qv per-head
    gemmw<<<dim3(8, 8, HH), 256, 2 * GSTG>>>(qh, ql, relh, rell, pQv, nobf, nobf,
        512, 512, 4096, 64,
        0, 64, 0, (long)UU * DDim, 0, 512, HH, nomask, pVrel, 512, 0);

    k_acat_p<<<(16 * TT * DDim + 255) / 256, 256>>>();

    // logits (128x128 tiles, proven config)
    k_logits_wmma<<<dim3(KVL / 128, TT / 128, 16), 256, 2 * LSTG>>>(mask, smask);

    // softmax: warp per row, causal chunk-skip
    k_softmax<<<16 * TT / 8, 256>>>();

    // attended = weights @ value, bf16 hi/lo output direct
    gemmw<<<dim3(1, 4, 16), 256, 2 * GSTG>>>(Wh, Wl, valh, vall, pAtt, atth, attl,
        KVL, 512, 512, KVL,
        (long)HH * TT * KVL, (long)TT * KVL,
        (long)KVL * 512, 64,
        (long)TT * 512, 64, HH, nomask, nobias, 0, 1);

    // out = attended @ output_W
    gemmw<<<dim3(8, 8, 1), 256, 2 * GSTG>>>(atth, attl, oWh, oWl, out, nobf, nobf,
        512, 512, 512, 512, 0, 0, 0, 0, 0, 0, 1, nomask, nobias, 0, 0);
}